// round 13
// baseline (speedup 1.0000x reference)
#include <cuda_runtime.h>
#include <cstdint>

#define D 128
#define MAX_E 640000
#define MAX_N 40000
#define SCALE 0.08838834764831845f  // 1/sqrt(128)
#define BM 64                        // nodes per GEMM block
#define BK 32                        // k-tile
#define APAD 68                      // A-tile smem row stride (floats)
#define EPW 8                        // edges per warp in edge kernels

// ---- scratch (device globals; no allocation allowed) ----
__device__ __align__(16) float g_summed[MAX_N * D];
__device__ __align__(16) float g_U[MAX_N * D];
__device__ __align__(16) float g_qk[MAX_N * D];
__device__ float g_sums[MAX_N];
__device__ __align__(16) float g_Mt[D * D];   // B layout: [l][t] = M[t][l]
__device__ __align__(16) float g_Wvo[D * D];  // B layout: [l][t]
__device__ float g_c[D];                      // Wk bq
__device__ float g_bvo[D];                    // bv Wo

// ---- K0: fold weight matrices + zero g_summed (grid-stride) ----
__global__ void k_precompute(const float* __restrict__ Wk,
                             const float* __restrict__ Wv, const float* __restrict__ bv,
                             const float* __restrict__ Wq, const float* __restrict__ bq,
                             const float* __restrict__ Wo, int N) {
    int l = blockIdx.x, t = threadIdx.x;
    if (blockIdx.y == 0) {
        float acc = 0.f;
        for (int j = 0; j < D; j++) acc += Wk[t * D + j] * Wq[l * D + j];
        g_Mt[l * D + t] = acc;
        if (l == 0) {
            float c = 0.f;
            for (int j = 0; j < D; j++) c += Wk[t * D + j] * bq[j];
            g_c[t] = c;
        }
    } else {
        float acc = 0.f;
        for (int i = 0; i < D; i++) acc += Wv[l * D + i] * Wo[i * D + t];
        g_Wvo[l * D + t] = acc;
        if (l == 0) {
            float b = 0.f;
            for (int i = 0; i < D; i++) b += bv[i] * Wo[i * D + t];
            g_bvo[t] = b;
        }
    }
    int gid = (blockIdx.y * gridDim.x + blockIdx.x) * blockDim.x + t;
    int tot4 = N * (D / 4);
    float4 z = make_float4(0.f, 0.f, 0.f, 0.f);
    for (int i = gid; i < tot4; i += gridDim.x * gridDim.y * blockDim.x)
        reinterpret_cast<float4*>(g_summed)[i] = z;
}

// ---- K2: summed[r] += m[e] — 8 edges per warp for MLP ----
__global__ void __launch_bounds__(256) k_segsum(const float4* __restrict__ msg,
                                                const int* __restrict__ recv, int E) {
    int w = (blockIdx.x * blockDim.x + threadIdx.x) >> 5;
    int lane = threadIdx.x & 31;
    int e0 = w * EPW;
    if (e0 >= E) return;
    int r[EPW];
    float4 m[EPW];
    #pragma unroll
    for (int j = 0; j < EPW; j++) {
        int e = min(e0 + j, E - 1);
        r[j] = __ldg(&recv[e]);
    }
    #pragma unroll
    for (int j = 0; j < EPW; j++) {
        int e = min(e0 + j, E - 1);
        m[j] = __ldg(&msg[(size_t)e * 32 + lane]);
    }
    #pragma unroll
    for (int j = 0; j < EPW; j++) {
        if (e0 + j < E) {
            float* dst = &g_summed[(size_t)r[j] * D + lane * 4];
            asm volatile("red.global.add.v4.f32 [%0], {%1,%2,%3,%4};"
                         :: "l"(dst), "f"(m[j].x), "f"(m[j].y), "f"(m[j].z), "f"(m[j].w) : "memory");
        }
    }
}

// ---- K3: qk = summed @ M^T + c — 64x128 tile, 8x4/thread, BK=32 ----
__global__ void __launch_bounds__(256) k_qk(int N) {
    __shared__ float As[BK][APAD];
    __shared__ float Bs[BK][D];
    int t = threadIdx.x;
    int lane = t & 31, warp = t >> 5;
    int nb0 = blockIdx.x * BM;
    int ar = t >> 2, ac4 = t & 3;

    float4 cb = __ldg(reinterpret_cast<const float4*>(&g_c[lane * 4]));
    float acc[8][4];
    #pragma unroll
    for (int i = 0; i < 8; i++) {
        acc[i][0] = cb.x; acc[i][1] = cb.y; acc[i][2] = cb.z; acc[i][3] = cb.w;
    }

    for (int k0 = 0; k0 < D; k0 += BK) {
        int n = nb0 + ar;
        #pragma unroll
        for (int i = 0; i < 2; i++) {
            int kc = ac4 + i * 4;
            float4 av = (n < N) ? __ldg(reinterpret_cast<const float4*>(
                                      &g_summed[(size_t)n * D + k0 + kc * 4]))
                                : make_float4(0.f, 0.f, 0.f, 0.f);
            As[kc * 4 + 0][ar] = av.x;
            As[kc * 4 + 1][ar] = av.y;
            As[kc * 4 + 2][ar] = av.z;
            As[kc * 4 + 3][ar] = av.w;
        }
        #pragma unroll
        for (int i = 0; i < 4; i++) {
            int idx = t + i * 256;
            int row = idx >> 5, col4 = idx & 31;
            *reinterpret_cast<float4*>(&Bs[row][col4 * 4]) =
                __ldg(reinterpret_cast<const float4*>(&g_Mt[(size_t)(k0 + row) * D + col4 * 4]));
        }
        __syncthreads();
        #pragma unroll
        for (int kk = 0; kk < BK; kk++) {
            float4 a0 = *reinterpret_cast<const float4*>(&As[kk][warp * 8]);
            float4 a1 = *reinterpret_cast<const float4*>(&As[kk][warp * 8 + 4]);
            float4 b  = *reinterpret_cast<const float4*>(&Bs[kk][lane * 4]);
            float a[8] = {a0.x, a0.y, a0.z, a0.w, a1.x, a1.y, a1.z, a1.w};
            #pragma unroll
            for (int i = 0; i < 8; i++) {
                acc[i][0] += a[i] * b.x;
                acc[i][1] += a[i] * b.y;
                acc[i][2] += a[i] * b.z;
                acc[i][3] += a[i] * b.w;
            }
        }
        __syncthreads();
    }
    #pragma unroll
    for (int i = 0; i < 8; i++) {
        int n = nb0 + warp * 8 + i;
        if (n < N) {
            *reinterpret_cast<float4*>(&g_qk[(size_t)n * D + lane * 4]) =
                make_float4(acc[i][0], acc[i][1], acc[i][2], acc[i][3]);
        }
    }
    float4 z = make_float4(0.f, 0.f, 0.f, 0.f);
    #pragma unroll
    for (int i = 0; i < 8; i++) {
        int idx = t + i * 256;
        int n = nb0 + (idx >> 5);
        if (n < N) reinterpret_cast<float4*>(g_U)[(size_t)n * (D / 4) + (idx & 31)] = z;
    }
    if (t < BM) {
        int n = nb0 + t;
        if (n < N) g_sums[n] = 0.f;
    }
}

__device__ __forceinline__ float dot4(float4 a, float4 b) {
    return a.x * b.x + a.y * b.y + a.z * b.z + a.w * b.w;
}

// ---- K4: fused scores + exp + weighted accumulation — 8 edges per warp ----
__global__ void __launch_bounds__(256) k_fused(const float4* __restrict__ msg,
                                               const int* __restrict__ recv, int E) {
    int w = (blockIdx.x * blockDim.x + threadIdx.x) >> 5;
    int lane = threadIdx.x & 31;
    int e0 = w * EPW;
    if (e0 >= E) return;
    const float4* qk4 = reinterpret_cast<const float4*>(g_qk);
    int r[EPW];
    float4 m[EPW], q[EPW];
    #pragma unroll
    for (int j = 0; j < EPW; j++) {
        int e = min(e0 + j, E - 1);
        r[j] = __ldg(&recv[e]);
    }
    #pragma unroll
    for (int j = 0; j < EPW; j++) {
        int e = min(e0 + j, E - 1);
        m[j] = __ldg(&msg[(size_t)e * 32 + lane]);
    }
    #pragma unroll
    for (int j = 0; j < EPW; j++)
        q[j] = __ldg(&qk4[(size_t)r[j] * 32 + lane]);
    float d[EPW];
    #pragma unroll
    for (int j = 0; j < EPW; j++) d[j] = dot4(m[j], q[j]);
    #pragma unroll
    for (int o = 16; o > 0; o >>= 1) {
        #pragma unroll
        for (int j = 0; j < EPW; j++)
            d[j] += __shfl_xor_sync(0xffffffffu, d[j], o);
    }
    #pragma unroll
    for (int j = 0; j < EPW; j++) {
        if (e0 + j < E) {
            float wt = __expf(d[j] * SCALE);
            float* dst = &g_U[(size_t)r[j] * D + lane * 4];
            asm volatile("red.global.add.v4.f32 [%0], {%1,%2,%3,%4};"
                         :: "l"(dst), "f"(wt * m[j].x), "f"(wt * m[j].y),
                            "f"(wt * m[j].z), "f"(wt * m[j].w) : "memory");
            if (lane == 0)
                asm volatile("red.global.add.f32 [%0], %1;"
                             :: "l"(&g_sums[r[j]]), "f"(wt) : "memory");
        }
    }
}

// ---- K5: out = (U/sum) @ Wvo + sa*bvo + bo — 64x128 tile, BK=32 ----
__global__ void __launch_bounds__(256) k_out(const float* __restrict__ bo,
                                             float* __restrict__ out, int N) {
    __shared__ float As[BK][APAD];
    __shared__ float Bs[BK][D];
    __shared__ float sinv[BM];
    __shared__ float ssa[BM];
    int t = threadIdx.x;
    int lane = t & 31, warp = t >> 5;
    int nb0 = blockIdx.x * BM;
    int ar = t >> 2, ac4 = t & 3;

    if (t < BM) {
        int n = nb0 + t;
        float s = (n < N) ? g_sums[n] : 0.f;
        sinv[t] = (s > 0.f) ? 1.f / s : 0.f;
        ssa[t] = (s > 0.f) ? 1.f : 0.f;
    }
    __syncthreads();

    float acc[8][4];
    #pragma unroll
    for (int i = 0; i < 8; i++)
        acc[i][0] = acc[i][1] = acc[i][2] = acc[i][3] = 0.f;

    float rinv = sinv[ar];
    for (int k0 = 0; k0 < D; k0 += BK) {
        int n = nb0 + ar;
        #pragma unroll
        for (int i = 0; i < 2; i++) {
            int kc = ac4 + i * 4;
            float4 av = (n < N) ? __ldg(reinterpret_cast<const float4*>(
                                      &g_U[(size_t)n * D + k0 + kc * 4]))
                                : make_float4(0.f, 0.f, 0.f, 0.f);
            As[kc * 4 + 0][ar] = av.x * rinv;
            As[kc * 4 + 1][ar] = av.y * rinv;
            As[kc * 4 + 2][ar] = av.z * rinv;
            As[kc * 4 + 3][ar] = av.w * rinv;
        }
        #pragma unroll
        for (int i = 0; i < 4; i++) {
            int idx = t + i * 256;
            int row = idx >> 5, col4 = idx & 31;
            *reinterpret_cast<float4*>(&Bs[row][col4 * 4]) =
                __ldg(reinterpret_cast<const float4*>(&g_Wvo[(size_t)(k0 + row) * D + col4 * 4]));
        }
        __syncthreads();
        #pragma unroll
        for (int kk = 0; kk < BK; kk++) {
            float4 a0 = *reinterpret_cast<const float4*>(&As[kk][warp * 8]);
            float4 a1 = *reinterpret_cast<const float4*>(&As[kk][warp * 8 + 4]);
            float4 b  = *reinterpret_cast<const float4*>(&Bs[kk][lane * 4]);
            float a[8] = {a0.x, a0.y, a0.z, a0.w, a1.x, a1.y, a1.z, a1.w};
            #pragma unroll
            for (int i = 0; i < 8; i++) {
                acc[i][0] += a[i] * b.x;
                acc[i][1] += a[i] * b.y;
                acc[i][2] += a[i] * b.z;
                acc[i][3] += a[i] * b.w;
            }
        }
        __syncthreads();
    }
    float4 bv4 = __ldg(reinterpret_cast<const float4*>(&g_bvo[lane * 4]));
    float4 bo4 = __ldg(reinterpret_cast<const float4*>(&bo[lane * 4]));
    #pragma unroll
    for (int i = 0; i < 8; i++) {
        int n = nb0 + warp * 8 + i;
        if (n < N) {
            float sa = ssa[warp * 8 + i];
            float4 o;
            o.x = acc[i][0] + sa * bv4.x + bo4.x;
            o.y = acc[i][1] + sa * bv4.y + bo4.y;
            o.z = acc[i][2] + sa * bv4.z + bo4.z;
            o.w = acc[i][3] + sa * bv4.w + bo4.w;
            *reinterpret_cast<float4*>(&out[(size_t)n * D + lane * 4]) = o;
        }
    }
}

extern "C" void kernel_launch(void* const* d_in, const int* in_sizes, int n_in,
                              void* d_out, int out_size) {
    const float* messages = (const float*)d_in[0];
    const int*   receivers = (const int*)d_in[1];
    int base = (n_in >= 11 && in_sizes[2] == 1) ? 3 : 2;
    const float* Wk = (const float*)d_in[base + 0];
    const float* Wv = (const float*)d_in[base + 2];
    const float* bv = (const float*)d_in[base + 3];
    const float* Wq = (const float*)d_in[base + 4];
    const float* bq = (const float*)d_in[base + 5];
    const float* Wo = (const float*)d_in[base + 6];
    const float* bo = (const float*)d_in[base + 7];

    int E = in_sizes[1];
    int N = out_size / D;
    float* out = (float*)d_out;

    k_precompute<<<dim3(D, 2), D>>>(Wk, Wv, bv, Wq, bq, Wo, N);
    int nwarps = (E + EPW - 1) / EPW;
    int eblocks = (nwarps * 32 + 255) / 256;
    k_segsum<<<eblocks, 256>>>((const float4*)messages, receivers, E);
    int gblocks = (N + BM - 1) / BM;
    k_qk<<<gblocks, 256>>>(N);
    k_fused<<<eblocks, 256>>>((const float4*)messages, receivers, E);
    k_out<<<gblocks, 256>>>(bo, out, N);
}

// round 14
// speedup vs baseline: 1.1261x; 1.1261x over previous
#include <cuda_runtime.h>
#include <cstdint>

#define D 128
#define MAX_E 640000
#define MAX_N 40000
#define SCALE 0.08838834764831845f  // 1/sqrt(128)
#define BM 64                        // nodes per GEMM block
#define BK 32                        // k-tile
#define APAD 68                      // A-tile smem row stride (floats)
#define EPW 4                        // edges per warp (measured optimum: 32 regs, 85% occ)

// ---- scratch (device globals; no allocation allowed) ----
__device__ __align__(16) float g_summed[MAX_N * D];
__device__ __align__(16) float g_U[MAX_N * D];
__device__ __align__(16) float g_qk[MAX_N * D];
__device__ float g_sums[MAX_N];
__device__ __align__(16) float g_Mt[D * D];   // B layout: [l][t] = M[t][l]
__device__ __align__(16) float g_Wvo[D * D];  // B layout: [l][t]
__device__ float g_c[D];                      // Wk bq
__device__ float g_bvo[D];                    // bv Wo

// streaming (evict-first) float4 load — keeps L2 for qk/atomic destinations
__device__ __forceinline__ float4 ldcs4(const float4* p) {
    float4 v;
    asm volatile("ld.global.cs.v4.f32 {%0,%1,%2,%3}, [%4];"
                 : "=f"(v.x), "=f"(v.y), "=f"(v.z), "=f"(v.w) : "l"(p));
    return v;
}

// ---- K0: fold weight matrices + zero g_summed (grid-stride) ----
__global__ void k_precompute(const float* __restrict__ Wk,
                             const float* __restrict__ Wv, const float* __restrict__ bv,
                             const float* __restrict__ Wq, const float* __restrict__ bq,
                             const float* __restrict__ Wo, int N) {
    int l = blockIdx.x, t = threadIdx.x;
    if (blockIdx.y == 0) {
        float acc = 0.f;
        for (int j = 0; j < D; j++) acc += Wk[t * D + j] * Wq[l * D + j];
        g_Mt[l * D + t] = acc;
        if (l == 0) {
            float c = 0.f;
            for (int j = 0; j < D; j++) c += Wk[t * D + j] * bq[j];
            g_c[t] = c;
        }
    } else {
        float acc = 0.f;
        for (int i = 0; i < D; i++) acc += Wv[l * D + i] * Wo[i * D + t];
        g_Wvo[l * D + t] = acc;
        if (l == 0) {
            float b = 0.f;
            for (int i = 0; i < D; i++) b += bv[i] * Wo[i * D + t];
            g_bvo[t] = b;
        }
    }
    int gid = (blockIdx.y * gridDim.x + blockIdx.x) * blockDim.x + t;
    int tot4 = N * (D / 4);
    float4 z = make_float4(0.f, 0.f, 0.f, 0.f);
    for (int i = gid; i < tot4; i += gridDim.x * gridDim.y * blockDim.x)
        reinterpret_cast<float4*>(g_summed)[i] = z;
}

// ---- K2: summed[r] += m[e] — 4 edges per warp, streaming msg loads ----
__global__ void __launch_bounds__(256) k_segsum(const float4* __restrict__ msg,
                                                const int* __restrict__ recv, int E) {
    int w = (blockIdx.x * blockDim.x + threadIdx.x) >> 5;
    int lane = threadIdx.x & 31;
    int e0 = w * EPW;
    if (e0 >= E) return;
    int r[EPW];
    float4 m[EPW];
    #pragma unroll
    for (int j = 0; j < EPW; j++) {
        int e = min(e0 + j, E - 1);
        r[j] = __ldg(&recv[e]);
    }
    #pragma unroll
    for (int j = 0; j < EPW; j++) {
        int e = min(e0 + j, E - 1);
        m[j] = ldcs4(&msg[(size_t)e * 32 + lane]);
    }
    #pragma unroll
    for (int j = 0; j < EPW; j++) {
        if (e0 + j < E) {
            float* dst = &g_summed[(size_t)r[j] * D + lane * 4];
            asm volatile("red.global.add.v4.f32 [%0], {%1,%2,%3,%4};"
                         :: "l"(dst), "f"(m[j].x), "f"(m[j].y), "f"(m[j].z), "f"(m[j].w) : "memory");
        }
    }
}

// ---- K3: qk = summed @ M^T + c — 64x128 tile, 8x4/thread, BK=32 ----
__global__ void __launch_bounds__(256) k_qk(int N) {
    __shared__ float As[BK][APAD];
    __shared__ float Bs[BK][D];
    int t = threadIdx.x;
    int lane = t & 31, warp = t >> 5;
    int nb0 = blockIdx.x * BM;
    int ar = t >> 2, ac4 = t & 3;

    float4 cb = __ldg(reinterpret_cast<const float4*>(&g_c[lane * 4]));
    float acc[8][4];
    #pragma unroll
    for (int i = 0; i < 8; i++) {
        acc[i][0] = cb.x; acc[i][1] = cb.y; acc[i][2] = cb.z; acc[i][3] = cb.w;
    }

    for (int k0 = 0; k0 < D; k0 += BK) {
        int n = nb0 + ar;
        #pragma unroll
        for (int i = 0; i < 2; i++) {
            int kc = ac4 + i * 4;
            float4 av = (n < N) ? __ldg(reinterpret_cast<const float4*>(
                                      &g_summed[(size_t)n * D + k0 + kc * 4]))
                                : make_float4(0.f, 0.f, 0.f, 0.f);
            As[kc * 4 + 0][ar] = av.x;
            As[kc * 4 + 1][ar] = av.y;
            As[kc * 4 + 2][ar] = av.z;
            As[kc * 4 + 3][ar] = av.w;
        }
        #pragma unroll
        for (int i = 0; i < 4; i++) {
            int idx = t + i * 256;
            int row = idx >> 5, col4 = idx & 31;
            *reinterpret_cast<float4*>(&Bs[row][col4 * 4]) =
                __ldg(reinterpret_cast<const float4*>(&g_Mt[(size_t)(k0 + row) * D + col4 * 4]));
        }
        __syncthreads();
        #pragma unroll
        for (int kk = 0; kk < BK; kk++) {
            float4 a0 = *reinterpret_cast<const float4*>(&As[kk][warp * 8]);
            float4 a1 = *reinterpret_cast<const float4*>(&As[kk][warp * 8 + 4]);
            float4 b  = *reinterpret_cast<const float4*>(&Bs[kk][lane * 4]);
            float a[8] = {a0.x, a0.y, a0.z, a0.w, a1.x, a1.y, a1.z, a1.w};
            #pragma unroll
            for (int i = 0; i < 8; i++) {
                acc[i][0] += a[i] * b.x;
                acc[i][1] += a[i] * b.y;
                acc[i][2] += a[i] * b.z;
                acc[i][3] += a[i] * b.w;
            }
        }
        __syncthreads();
    }
    #pragma unroll
    for (int i = 0; i < 8; i++) {
        int n = nb0 + warp * 8 + i;
        if (n < N) {
            *reinterpret_cast<float4*>(&g_qk[(size_t)n * D + lane * 4]) =
                make_float4(acc[i][0], acc[i][1], acc[i][2], acc[i][3]);
        }
    }
    float4 z = make_float4(0.f, 0.f, 0.f, 0.f);
    #pragma unroll
    for (int i = 0; i < 8; i++) {
        int idx = t + i * 256;
        int n = nb0 + (idx >> 5);
        if (n < N) reinterpret_cast<float4*>(g_U)[(size_t)n * (D / 4) + (idx & 31)] = z;
    }
    if (t < BM) {
        int n = nb0 + t;
        if (n < N) g_sums[n] = 0.f;
    }
}

__device__ __forceinline__ float dot4(float4 a, float4 b) {
    return a.x * b.x + a.y * b.y + a.z * b.z + a.w * b.w;
}

// ---- K4: fused scores + exp + weighted accumulation — 4 edges per warp ----
__global__ void __launch_bounds__(256) k_fused(const float4* __restrict__ msg,
                                               const int* __restrict__ recv, int E) {
    int w = (blockIdx.x * blockDim.x + threadIdx.x) >> 5;
    int lane = threadIdx.x & 31;
    int e0 = w * EPW;
    if (e0 >= E) return;
    const float4* qk4 = reinterpret_cast<const float4*>(g_qk);
    int r[EPW];
    float4 m[EPW], q[EPW];
    #pragma unroll
    for (int j = 0; j < EPW; j++) {
        int e = min(e0 + j, E - 1);
        r[j] = __ldg(&recv[e]);
    }
    #pragma unroll
    for (int j = 0; j < EPW; j++) {
        int e = min(e0 + j, E - 1);
        m[j] = ldcs4(&msg[(size_t)e * 32 + lane]);
    }
    #pragma unroll
    for (int j = 0; j < EPW; j++)
        q[j] = __ldg(&qk4[(size_t)r[j] * 32 + lane]);
    float d[EPW];
    #pragma unroll
    for (int j = 0; j < EPW; j++) d[j] = dot4(m[j], q[j]);
    #pragma unroll
    for (int o = 16; o > 0; o >>= 1) {
        #pragma unroll
        for (int j = 0; j < EPW; j++)
            d[j] += __shfl_xor_sync(0xffffffffu, d[j], o);
    }
    #pragma unroll
    for (int j = 0; j < EPW; j++) {
        if (e0 + j < E) {
            float wt = __expf(d[j] * SCALE);
            float* dst = &g_U[(size_t)r[j] * D + lane * 4];
            asm volatile("red.global.add.v4.f32 [%0], {%1,%2,%3,%4};"
                         :: "l"(dst), "f"(wt * m[j].x), "f"(wt * m[j].y),
                            "f"(wt * m[j].z), "f"(wt * m[j].w) : "memory");
            if (lane == 0)
                asm volatile("red.global.add.f32 [%0], %1;"
                             :: "l"(&g_sums[r[j]]), "f"(wt) : "memory");
        }
    }
}

// ---- K5: out = (U/sum) @ Wvo + sa*bvo + bo — 64x128 tile, BK=32 ----
__global__ void __launch_bounds__(256) k_out(const float* __restrict__ bo,
                                             float* __restrict__ out, int N) {
    __shared__ float As[BK][APAD];
    __shared__ float Bs[BK][D];
    __shared__ float sinv[BM];
    __shared__ float ssa[BM];
    int t = threadIdx.x;
    int lane = t & 31, warp = t >> 5;
    int nb0 = blockIdx.x * BM;
    int ar = t >> 2, ac4 = t & 3;

    if (t < BM) {
        int n = nb0 + t;
        float s = (n < N) ? g_sums[n] : 0.f;
        sinv[t] = (s > 0.f) ? 1.f / s : 0.f;
        ssa[t] = (s > 0.f) ? 1.f : 0.f;
    }
    __syncthreads();

    float acc[8][4];
    #pragma unroll
    for (int i = 0; i < 8; i++)
        acc[i][0] = acc[i][1] = acc[i][2] = acc[i][3] = 0.f;

    float rinv = sinv[ar];
    for (int k0 = 0; k0 < D; k0 += BK) {
        int n = nb0 + ar;
        #pragma unroll
        for (int i = 0; i < 2; i++) {
            int kc = ac4 + i * 4;
            float4 av = (n < N) ? __ldg(reinterpret_cast<const float4*>(
                                      &g_U[(size_t)n * D + k0 + kc * 4]))
                                : make_float4(0.f, 0.f, 0.f, 0.f);
            As[kc * 4 + 0][ar] = av.x * rinv;
            As[kc * 4 + 1][ar] = av.y * rinv;
            As[kc * 4 + 2][ar] = av.z * rinv;
            As[kc * 4 + 3][ar] = av.w * rinv;
        }
        #pragma unroll
        for (int i = 0; i < 4; i++) {
            int idx = t + i * 256;
            int row = idx >> 5, col4 = idx & 31;
            *reinterpret_cast<float4*>(&Bs[row][col4 * 4]) =
                __ldg(reinterpret_cast<const float4*>(&g_Wvo[(size_t)(k0 + row) * D + col4 * 4]));
        }
        __syncthreads();
        #pragma unroll
        for (int kk = 0; kk < BK; kk++) {
            float4 a0 = *reinterpret_cast<const float4*>(&As[kk][warp * 8]);
            float4 a1 = *reinterpret_cast<const float4*>(&As[kk][warp * 8 + 4]);
            float4 b  = *reinterpret_cast<const float4*>(&Bs[kk][lane * 4]);
            float a[8] = {a0.x, a0.y, a0.z, a0.w, a1.x, a1.y, a1.z, a1.w};
            #pragma unroll
            for (int i = 0; i < 8; i++) {
                acc[i][0] += a[i] * b.x;
                acc[i][1] += a[i] * b.y;
                acc[i][2] += a[i] * b.z;
                acc[i][3] += a[i] * b.w;
            }
        }
        __syncthreads();
    }
    float4 bv4 = __ldg(reinterpret_cast<const float4*>(&g_bvo[lane * 4]));
    float4 bo4 = __ldg(reinterpret_cast<const float4*>(&bo[lane * 4]));
    #pragma unroll
    for (int i = 0; i < 8; i++) {
        int n = nb0 + warp * 8 + i;
        if (n < N) {
            float sa = ssa[warp * 8 + i];
            float4 o;
            o.x = acc[i][0] + sa * bv4.x + bo4.x;
            o.y = acc[i][1] + sa * bv4.y + bo4.y;
            o.z = acc[i][2] + sa * bv4.z + bo4.z;
            o.w = acc[i][3] + sa * bv4.w + bo4.w;
            *reinterpret_cast<float4*>(&out[(size_t)n * D + lane * 4]) = o;
        }
    }
}

extern "C" void kernel_launch(void* const* d_in, const int* in_sizes, int n_in,
                              void* d_out, int out_size) {
    const float* messages = (const float*)d_in[0];
    const int*   receivers = (const int*)d_in[1];
    int base = (n_in >= 11 && in_sizes[2] == 1) ? 3 : 2;
    const float* Wk = (const float*)d_in[base + 0];
    const float* Wv = (const float*)d_in[base + 2];
    const float* bv = (const float*)d_in[base + 3];
    const float* Wq = (const float*)d_in[base + 4];
    const float* bq = (const float*)d_in[base + 5];
    const float* Wo = (const float*)d_in[base + 6];
    const float* bo = (const float*)d_in[base + 7];

    int E = in_sizes[1];
    int N = out_size / D;
    float* out = (float*)d_out;

    k_precompute<<<dim3(D, 2), D>>>(Wk, Wv, bv, Wq, bq, Wo, N);
    int nwarps = (E + EPW - 1) / EPW;
    int eblocks = (nwarps * 32 + 255) / 256;
    k_segsum<<<eblocks, 256>>>((const float4*)messages, receivers, E);
    int gblocks = (N + BM - 1) / BM;
    k_qk<<<gblocks, 256>>>(N);
    k_fused<<<eblocks, 256>>>((const float4*)messages, receivers, E);
    k_out<<<gblocks, 256>>>(bo, out, N);
}